// round 5
// baseline (speedup 1.0000x reference)
#include <cuda_runtime.h>
#include <math.h>

// Problem constants (fixed-shape instance)
#define BB 1024
#define SS 512
#define DD 768
#define FF (3*DD)      // 2304
#define H1 256
#define H2 64
#define NC 4
#define BT 8           // batch rows per CTA -> 128 CTAs
#define NT 512         // threads per CTA
#define KT 32          // k-tile rows of W1 per cp.async stage
#define NTILE (FF/KT)  // 72

// ---------------------------------------------------------------------------
// cp.async helpers (LDGSTS)
// ---------------------------------------------------------------------------
__device__ __forceinline__ void cp_async16(float* smem_dst, const float* gmem_src) {
    unsigned s = (unsigned)__cvta_generic_to_shared(smem_dst);
    asm volatile("cp.async.cg.shared.global [%0], [%1], 16;\n" :: "r"(s), "l"(gmem_src));
}
__device__ __forceinline__ void cp_commit() {
    asm volatile("cp.async.commit_group;\n" ::: "memory");
}
template<int N>
__device__ __forceinline__ void cp_wait() {
    asm volatile("cp.async.wait_group %0;\n" :: "n"(N) : "memory");
}

// ---------------------------------------------------------------------------
// Fused kernel: span-mean features + 3-layer MLP + softmax.
// 128 CTAs x 512 threads. Dynamic smem:
//   fs   [BT*FF]      feat tile (written directly by feat phase)  73728 B
//   wbuf [2][KT*H1]   W1 double buffer (cp.async)                 65536 B
// Static smem: h1s 8KB, h2s 2KB.  Total ~149.5 KB -> 1 CTA/SM, 16 warps.
// ---------------------------------------------------------------------------
__global__ __launch_bounds__(NT) void fused_kernel(
    const float* __restrict__ x,
    const int* __restrict__ e1,
    const int* __restrict__ e2,
    const float* __restrict__ W1, const float* __restrict__ b1,
    const float* __restrict__ W2, const float* __restrict__ b2,
    const float* __restrict__ W3, const float* __restrict__ b3,
    float* __restrict__ out)
{
    extern __shared__ float fs[];          // [BT][FF]
    float* wbuf = fs + BT*FF;              // [2][KT*H1]
    __shared__ float h1s[BT][H1];
    __shared__ float h2s[BT][H2];

    const int b0  = blockIdx.x * BT;
    const int tid = threadIdx.x;

    // ---- start W1 tile 0 prefetch immediately (hides under feat phase) ----
    {
        #pragma unroll
        for (int i = 0; i < KT*H1/4/NT; ++i)   // 4 float4 per thread
            cp_async16(wbuf + (tid + i*NT)*4, W1 + (tid + i*NT)*4);
        cp_commit();
    }

    // =====================================================================
    // Phase 1: feat = [mean(e1 span) | mean(e2 span) | cls] for 8 elems.
    // Threads 0..383: two 192-lane groups, each owns one elem per round.
    // Thread (grp, lane) does ALL work for its (elem, float4-lane) -> no
    // intra-phase syncs needed; one __syncthreads before layer 1.
    // =====================================================================
    {
        const int grp  = tid / 192;        // 0,1 active; 2 idle
        const int lane = tid % 192;        // float4 lane over D=768

        if (grp < 2) {
            #pragma unroll
            for (int round = 0; round < BT/2; ++round) {
                const int i = round*2 + grp;       // elem within CTA
                const int b = b0 + i;

                int lo1 = e1[2*b]; int hi1 = max(e1[2*b+1], lo1 + 1);
                int lo2 = e2[2*b]; int hi2 = max(e2[2*b+1], lo2 + 1);

                const float4* __restrict__ xb =
                    reinterpret_cast<const float4*>(x) + (size_t)b * (SS*(DD/4));

                float4 s1 = make_float4(0.f,0.f,0.f,0.f);
                float4 s2 = make_float4(0.f,0.f,0.f,0.f);

                auto rsum = [&](int a, int c, float4& acc) {
                    #pragma unroll 4
                    for (int s = a; s < c; ++s) {
                        float4 v = __ldcs(&xb[(size_t)s*(DD/4) + lane]);
                        acc.x += v.x; acc.y += v.y; acc.z += v.z; acc.w += v.w;
                    }
                };

                const int mlo = max(lo1, lo2);
                const int mhi = min(hi1, hi2);
                if (mlo < mhi) {   // overlapping spans: read overlap once
                    float4 ov = make_float4(0.f,0.f,0.f,0.f);
                    rsum(mlo, mhi, ov);
                    rsum(lo1, mlo, s1); rsum(mhi, hi1, s1);
                    rsum(lo2, mlo, s2); rsum(mhi, hi2, s2);
                    s1.x += ov.x; s1.y += ov.y; s1.z += ov.z; s1.w += ov.w;
                    s2.x += ov.x; s2.y += ov.y; s2.z += ov.z; s2.w += ov.w;
                } else {
                    rsum(lo1, hi1, s1);
                    rsum(lo2, hi2, s2);
                }

                float4 cls = xb[lane];     // row 0 (spans start >= 1)

                const float r1 = 1.f / (float)(hi1 - lo1);
                const float r2 = 1.f / (float)(hi2 - lo2);

                float4* __restrict__ fb = reinterpret_cast<float4*>(fs + i*FF);
                fb[lane]            = make_float4(s1.x*r1, s1.y*r1, s1.z*r1, s1.w*r1);
                fb[(DD/4)   + lane] = make_float4(s2.x*r2, s2.y*r2, s2.z*r2, s2.w*r2);
                fb[2*(DD/4) + lane] = cls;
            }
        }
    }
    __syncthreads();

    // =====================================================================
    // Phase 2: layer 1  [8,2304] @ [2304,256].
    // Thread -> (col = tid&255, batch-group g4 = (tid>>8)*4). Both groups
    // consume the SAME W1 tile stream: one cp.async double-buffer pipeline.
    // Per warp per k4-step: 8 LDS + 16 FFMA -> fma-bound at 4 warps/SMSP.
    // =====================================================================
    {
        const int col = tid & (H1-1);
        const int g4  = (tid >> 8) * 4;

        float acc[4] = {0.f, 0.f, 0.f, 0.f};

        for (int t = 0; t < NTILE; ++t) {
            if (t + 1 < NTILE) {
                const float* src = W1 + (size_t)(t+1)*KT*H1;
                float* dst = wbuf + ((t+1)&1)*KT*H1;
                #pragma unroll
                for (int i = 0; i < KT*H1/4/NT; ++i)
                    cp_async16(dst + (tid + i*NT)*4, src + (tid + i*NT)*4);
                cp_commit();
                cp_wait<1>();          // tile t complete
            } else {
                cp_wait<0>();
            }
            __syncthreads();

            const float* ws = wbuf + (t&1)*KT*H1;
            const int kbase = t*KT;
            #pragma unroll
            for (int kk = 0; kk < KT; kk += 4) {
                const float w0 = ws[(kk+0)*H1 + col];
                const float w1 = ws[(kk+1)*H1 + col];
                const float w2 = ws[(kk+2)*H1 + col];
                const float w3 = ws[(kk+3)*H1 + col];
                #pragma unroll
                for (int i = 0; i < 4; ++i) {
                    float4 f = *reinterpret_cast<const float4*>(
                        &fs[(g4+i)*FF + kbase + kk]);
                    acc[i] = fmaf(f.x, w0, acc[i]);
                    acc[i] = fmaf(f.y, w1, acc[i]);
                    acc[i] = fmaf(f.z, w2, acc[i]);
                    acc[i] = fmaf(f.w, w3, acc[i]);
                }
            }
            __syncthreads();
        }
        const float bb = b1[col];
        #pragma unroll
        for (int i = 0; i < 4; ++i)
            h1s[g4+i][col] = fmaxf(acc[i] + bb, 0.f);
    }
    __syncthreads();

    // =====================================================================
    // Phase 3: layer 2  [8,256] @ [256,64]. One thread per (elem, col).
    // =====================================================================
    {
        const int j = tid & (H2-1);
        const int i = tid >> 6;            // 0..7
        float a = 0.f;
        #pragma unroll 4
        for (int k = 0; k < H1; ++k)
            a = fmaf(h1s[i][k], W2[k*H2 + j], a);
        h2s[i][j] = fmaxf(a + b2[j], 0.f);
    }
    __syncthreads();

    // =====================================================================
    // Phase 4: layer 3 + softmax. One thread per batch row.
    // =====================================================================
    if (tid < BT) {
        const int i = tid;
        float l0 = b3[0], l1 = b3[1], l2 = b3[2], l3 = b3[3];
        #pragma unroll 8
        for (int k = 0; k < H2; ++k) {
            const float h = h2s[i][k];
            l0 = fmaf(h, W3[k*NC+0], l0);
            l1 = fmaf(h, W3[k*NC+1], l1);
            l2 = fmaf(h, W3[k*NC+2], l2);
            l3 = fmaf(h, W3[k*NC+3], l3);
        }
        float m = fmaxf(fmaxf(l0,l1), fmaxf(l2,l3));
        float e0 = expf(l0 - m), e1x = expf(l1 - m),
              e2x = expf(l2 - m), e3 = expf(l3 - m);
        float inv = 1.f / (e0 + e1x + e2x + e3);
        float* o = out + (size_t)(b0 + i) * NC;
        o[0] = e0*inv; o[1] = e1x*inv; o[2] = e2x*inv; o[3] = e3*inv;
    }
}

// ---------------------------------------------------------------------------
extern "C" void kernel_launch(void* const* d_in, const int* in_sizes, int n_in,
                              void* d_out, int out_size)
{
    const float* x   = (const float*)d_in[0];
    const int*   e1  = (const int*)  d_in[1];
    const int*   e2  = (const int*)  d_in[2];
    const float* W1  = (const float*)d_in[3];
    const float* b1  = (const float*)d_in[4];
    const float* W2  = (const float*)d_in[5];
    const float* b2  = (const float*)d_in[6];
    const float* W3  = (const float*)d_in[7];
    const float* b3  = (const float*)d_in[8];
    float* out = (float*)d_out;

    static int smem_set = 0;
    const int smem_bytes = (BT*FF + 2*KT*H1) * (int)sizeof(float);  // 139264
    if (!smem_set) {
        cudaFuncSetAttribute(fused_kernel,
            cudaFuncAttributeMaxDynamicSharedMemorySize, smem_bytes);
        smem_set = 1;
    }

    fused_kernel<<<BB/BT, NT, smem_bytes>>>(x, e1, e2, W1, b1, W2, b2, W3, b3, out);
}

// round 6
// speedup vs baseline: 2.9301x; 2.9301x over previous
#include <cuda_runtime.h>
#include <math.h>

// Problem constants (fixed-shape instance)
#define BB 1024
#define SS 512
#define DD 768
#define FF (3*DD)      // 2304
#define H1 256
#define H2 64
#define NC 4
#define BT 8           // batch rows per MLP CTA -> 128 CTAs
#define NT 512         // MLP threads per CTA
#define KT 32          // k-tile rows of W1 per cp.async stage
#define NTILE (FF/KT)  // 72
#define FG 4           // feat kernel row-groups
#define FNT (FG*192)   // 768 feat threads

// Scratch for feat = [e1 | e2 | cls], 1024 x 2304 fp32 (9.4 MB)
__device__ float g_feat[BB * FF];

// ---------------------------------------------------------------------------
// cp.async helpers (LDGSTS)
// ---------------------------------------------------------------------------
__device__ __forceinline__ void cp_async16(float* smem_dst, const float* gmem_src) {
    unsigned s = (unsigned)__cvta_generic_to_shared(smem_dst);
    asm volatile("cp.async.cg.shared.global [%0], [%1], 16;\n" :: "r"(s), "l"(gmem_src));
}
__device__ __forceinline__ void cp_commit() {
    asm volatile("cp.async.commit_group;\n" ::: "memory");
}
template<int N>
__device__ __forceinline__ void cp_wait() {
    asm volatile("cp.async.wait_group %0;\n" :: "n"(N) : "memory");
}

// ---------------------------------------------------------------------------
// Kernel 1: span means + cls. One CTA per batch element, 768 threads =
// 4 row-groups x 192 float4-lanes. Group g sums rows a+g, a+g+4, ... of each
// union sub-range -> 4x the outstanding loads of the R2 version and 4x
// shorter CTAs (smooths span-length load imbalance). Partials combined in
// smem, reduced by the first 192 threads.
// ---------------------------------------------------------------------------
__global__ __launch_bounds__(FNT) void feat_kernel(
    const float* __restrict__ x,
    const int* __restrict__ e1,
    const int* __restrict__ e2)
{
    __shared__ float4 p1[FG][192];
    __shared__ float4 p2[FG][192];

    const int b    = blockIdx.x;
    const int tid  = threadIdx.x;
    const int g    = tid / 192;
    const int lane = tid % 192;

    int lo1 = e1[2*b]; int hi1 = max(e1[2*b+1], lo1 + 1);
    int lo2 = e2[2*b]; int hi2 = max(e2[2*b+1], lo2 + 1);

    const float4* __restrict__ xb =
        reinterpret_cast<const float4*>(x) + (size_t)b * (SS*(DD/4));

    float4 s1 = make_float4(0.f,0.f,0.f,0.f);
    float4 s2 = make_float4(0.f,0.f,0.f,0.f);

    // strided range-sum: this group's share of rows [a,c)
    auto rsum = [&](int a, int c, float4& acc) {
        #pragma unroll 4
        for (int s = a + g; s < c; s += FG) {
            float4 v = __ldcs(&xb[(size_t)s*(DD/4) + lane]);
            acc.x += v.x; acc.y += v.y; acc.z += v.z; acc.w += v.w;
        }
    };

    const int mlo = max(lo1, lo2);
    const int mhi = min(hi1, hi2);
    if (mlo < mhi) {          // overlapping spans: read overlap once
        float4 ov = make_float4(0.f,0.f,0.f,0.f);
        rsum(mlo, mhi, ov);
        rsum(lo1, mlo, s1); rsum(mhi, hi1, s1);
        rsum(lo2, mlo, s2); rsum(mhi, hi2, s2);
        s1.x += ov.x; s1.y += ov.y; s1.z += ov.z; s1.w += ov.w;
        s2.x += ov.x; s2.y += ov.y; s2.z += ov.z; s2.w += ov.w;
    } else {
        rsum(lo1, hi1, s1);
        rsum(lo2, hi2, s2);
    }

    p1[g][lane] = s1;
    p2[g][lane] = s2;
    __syncthreads();

    if (tid < 192) {
        float4 a1 = p1[0][lane], a2 = p2[0][lane];
        #pragma unroll
        for (int gg = 1; gg < FG; ++gg) {
            float4 q1 = p1[gg][lane], q2 = p2[gg][lane];
            a1.x += q1.x; a1.y += q1.y; a1.z += q1.z; a1.w += q1.w;
            a2.x += q2.x; a2.y += q2.y; a2.z += q2.z; a2.w += q2.w;
        }
        const float r1 = 1.f / (float)(hi1 - lo1);
        const float r2 = 1.f / (float)(hi2 - lo2);
        float4 cls = xb[lane];           // row 0 (spans start >= 1)

        float4* __restrict__ fb = reinterpret_cast<float4*>(g_feat + (size_t)b*FF);
        fb[lane]            = make_float4(a1.x*r1, a1.y*r1, a1.z*r1, a1.w*r1);
        fb[(DD/4)   + lane] = make_float4(a2.x*r2, a2.y*r2, a2.z*r2, a2.w*r2);
        fb[2*(DD/4) + lane] = cls;
    }
}

// ---------------------------------------------------------------------------
// Kernel 2: fused 3-layer MLP + softmax. 128 CTAs x 512 threads, BT=8.
// Layer 1: thread -> (col = tid&255, batch-group (tid>>8)*4); both 256-thread
// halves consume the same cp.async W1 double-buffer. 16 warps/SM.
// Dynamic smem: fs [BT*FF] 73728 B + wbuf [2][KT*H1] 65536 B.
// ---------------------------------------------------------------------------
__global__ __launch_bounds__(NT) void mlp_kernel(
    const float* __restrict__ W1, const float* __restrict__ b1,
    const float* __restrict__ W2, const float* __restrict__ b2,
    const float* __restrict__ W3, const float* __restrict__ b3,
    float* __restrict__ out)
{
    extern __shared__ float fs[];          // [BT][FF]
    float* wbuf = fs + BT*FF;              // [2][KT*H1]
    __shared__ float h1s[BT][H1];
    __shared__ float h2s[BT][H2];

    const int b0  = blockIdx.x * BT;
    const int tid = threadIdx.x;

    // --- start W1 tile 0 prefetch immediately ---
    {
        #pragma unroll
        for (int i = 0; i < KT*H1/4/NT; ++i)   // 4 float4 per thread
            cp_async16(wbuf + (tid + i*NT)*4, W1 + (tid + i*NT)*4);
        cp_commit();
    }

    // --- load feat tile (coalesced float4 copy), overlaps with tile-0 fetch ---
    {
        const float4* __restrict__ src =
            reinterpret_cast<const float4*>(g_feat + (size_t)b0 * FF);
        float4* __restrict__ dst = reinterpret_cast<float4*>(fs);
        #pragma unroll
        for (int i = 0; i < BT*FF/4/NT; ++i)   // 9 per thread
            dst[tid + i*NT] = src[tid + i*NT];
    }

    // --- layer 1: [8,2304] @ [2304,256] ---
    {
        const int col = tid & (H1-1);
        const int g4  = (tid >> 8) * 4;

        float acc[4] = {0.f, 0.f, 0.f, 0.f};

        for (int t = 0; t < NTILE; ++t) {
            if (t + 1 < NTILE) {
                const float* src = W1 + (size_t)(t+1)*KT*H1;
                float* dst = wbuf + ((t+1)&1)*KT*H1;
                #pragma unroll
                for (int i = 0; i < KT*H1/4/NT; ++i)
                    cp_async16(dst + (tid + i*NT)*4, src + (tid + i*NT)*4);
                cp_commit();
                cp_wait<1>();          // tile t complete
            } else {
                cp_wait<0>();
            }
            __syncthreads();

            const float* ws = wbuf + (t&1)*KT*H1;
            const int kbase = t*KT;
            #pragma unroll
            for (int kk = 0; kk < KT; kk += 4) {
                const float w0 = ws[(kk+0)*H1 + col];
                const float w1 = ws[(kk+1)*H1 + col];
                const float w2 = ws[(kk+2)*H1 + col];
                const float w3 = ws[(kk+3)*H1 + col];
                #pragma unroll
                for (int i = 0; i < 4; ++i) {
                    float4 f = *reinterpret_cast<const float4*>(
                        &fs[(g4+i)*FF + kbase + kk]);
                    acc[i] = fmaf(f.x, w0, acc[i]);
                    acc[i] = fmaf(f.y, w1, acc[i]);
                    acc[i] = fmaf(f.z, w2, acc[i]);
                    acc[i] = fmaf(f.w, w3, acc[i]);
                }
            }
            __syncthreads();
        }
        const float bb = b1[col];
        #pragma unroll
        for (int i = 0; i < 4; ++i)
            h1s[g4+i][col] = fmaxf(acc[i] + bb, 0.f);
    }
    __syncthreads();

    // --- layer 2: [8,256] @ [256,64]; one thread per (elem, col) ---
    {
        const int j = tid & (H2-1);
        const int i = tid >> 6;            // 0..7
        float a = 0.f;
        #pragma unroll 4
        for (int k = 0; k < H1; ++k)
            a = fmaf(h1s[i][k], W2[k*H2 + j], a);
        h2s[i][j] = fmaxf(a + b2[j], 0.f);
    }
    __syncthreads();

    // --- layer 3 + softmax: one thread per batch row ---
    if (tid < BT) {
        const int i = tid;
        float l0 = b3[0], l1 = b3[1], l2 = b3[2], l3 = b3[3];
        #pragma unroll 8
        for (int k = 0; k < H2; ++k) {
            const float h = h2s[i][k];
            l0 = fmaf(h, W3[k*NC+0], l0);
            l1 = fmaf(h, W3[k*NC+1], l1);
            l2 = fmaf(h, W3[k*NC+2], l2);
            l3 = fmaf(h, W3[k*NC+3], l3);
        }
        float m = fmaxf(fmaxf(l0,l1), fmaxf(l2,l3));
        float e0 = expf(l0 - m), e1x = expf(l1 - m),
              e2x = expf(l2 - m), e3 = expf(l3 - m);
        float inv = 1.f / (e0 + e1x + e2x + e3);
        float* o = out + (size_t)(b0 + i) * NC;
        o[0] = e0*inv; o[1] = e1x*inv; o[2] = e2x*inv; o[3] = e3*inv;
    }
}

// ---------------------------------------------------------------------------
extern "C" void kernel_launch(void* const* d_in, const int* in_sizes, int n_in,
                              void* d_out, int out_size)
{
    const float* x   = (const float*)d_in[0];
    const int*   e1  = (const int*)  d_in[1];
    const int*   e2  = (const int*)  d_in[2];
    const float* W1  = (const float*)d_in[3];
    const float* b1  = (const float*)d_in[4];
    const float* W2  = (const float*)d_in[5];
    const float* b2  = (const float*)d_in[6];
    const float* W3  = (const float*)d_in[7];
    const float* b3  = (const float*)d_in[8];
    float* out = (float*)d_out;

    static int smem_set = 0;
    const int smem_bytes = (BT*FF + 2*KT*H1) * (int)sizeof(float);  // 139264
    if (!smem_set) {
        cudaFuncSetAttribute(mlp_kernel,
            cudaFuncAttributeMaxDynamicSharedMemorySize, smem_bytes);
        smem_set = 1;
    }

    feat_kernel<<<BB, FNT>>>(x, e1, e2);
    mlp_kernel<<<BB/BT, NT, smem_bytes>>>(W1, b1, W2, b2, W3, b3, out);
}

// round 7
// speedup vs baseline: 2.9542x; 1.0082x over previous
#include <cuda_runtime.h>
#include <math.h>

// Problem constants (fixed-shape instance)
#define BB 1024
#define SS 512
#define DD 768
#define FF (3*DD)      // 2304
#define H1 256
#define H2 64
#define NC 4
#define BT 8           // batch rows per MLP CTA -> 128 CTAs
#define NT 512         // MLP threads per CTA
#define KT 32          // k-tile rows of W1 per cp.async stage
#define NTILE (FF/KT)  // 72
#define FG 4           // feat kernel row-groups
#define FNT (FG*192)   // 768 feat threads

// Scratch for feat = [e1 | e2 | cls], 1024 x 2304 fp32 (9.4 MB)
__device__ float g_feat[BB * FF];

// ---------------------------------------------------------------------------
// cp.async helpers (LDGSTS)
// ---------------------------------------------------------------------------
__device__ __forceinline__ void cp_async16(float* smem_dst, const float* gmem_src) {
    unsigned s = (unsigned)__cvta_generic_to_shared(smem_dst);
    asm volatile("cp.async.cg.shared.global [%0], [%1], 16;\n" :: "r"(s), "l"(gmem_src));
}
__device__ __forceinline__ void cp_commit() {
    asm volatile("cp.async.commit_group;\n" ::: "memory");
}
template<int N>
__device__ __forceinline__ void cp_wait() {
    asm volatile("cp.async.wait_group %0;\n" :: "n"(N) : "memory");
}

// ---------------------------------------------------------------------------
// Kernel 1: span means + cls. One CTA per batch element, 768 threads =
// 4 row-groups x 192 float4-lanes (at HBM roofline; unchanged from R6).
// ---------------------------------------------------------------------------
__global__ __launch_bounds__(FNT) void feat_kernel(
    const float* __restrict__ x,
    const int* __restrict__ e1,
    const int* __restrict__ e2)
{
    __shared__ float4 p1[FG][192];
    __shared__ float4 p2[FG][192];

    const int b    = blockIdx.x;
    const int tid  = threadIdx.x;
    const int g    = tid / 192;
    const int lane = tid % 192;

    int lo1 = e1[2*b]; int hi1 = max(e1[2*b+1], lo1 + 1);
    int lo2 = e2[2*b]; int hi2 = max(e2[2*b+1], lo2 + 1);

    const float4* __restrict__ xb =
        reinterpret_cast<const float4*>(x) + (size_t)b * (SS*(DD/4));

    float4 s1 = make_float4(0.f,0.f,0.f,0.f);
    float4 s2 = make_float4(0.f,0.f,0.f,0.f);

    auto rsum = [&](int a, int c, float4& acc) {
        #pragma unroll 4
        for (int s = a + g; s < c; s += FG) {
            float4 v = __ldcs(&xb[(size_t)s*(DD/4) + lane]);
            acc.x += v.x; acc.y += v.y; acc.z += v.z; acc.w += v.w;
        }
    };

    const int mlo = max(lo1, lo2);
    const int mhi = min(hi1, hi2);
    if (mlo < mhi) {          // overlapping spans: read overlap once
        float4 ov = make_float4(0.f,0.f,0.f,0.f);
        rsum(mlo, mhi, ov);
        rsum(lo1, mlo, s1); rsum(mhi, hi1, s1);
        rsum(lo2, mlo, s2); rsum(mhi, hi2, s2);
        s1.x += ov.x; s1.y += ov.y; s1.z += ov.z; s1.w += ov.w;
        s2.x += ov.x; s2.y += ov.y; s2.z += ov.z; s2.w += ov.w;
    } else {
        rsum(lo1, hi1, s1);
        rsum(lo2, hi2, s2);
    }

    p1[g][lane] = s1;
    p2[g][lane] = s2;
    __syncthreads();

    if (tid < 192) {
        float4 a1 = p1[0][lane], a2 = p2[0][lane];
        #pragma unroll
        for (int gg = 1; gg < FG; ++gg) {
            float4 q1 = p1[gg][lane], q2 = p2[gg][lane];
            a1.x += q1.x; a1.y += q1.y; a1.z += q1.z; a1.w += q1.w;
            a2.x += q2.x; a2.y += q2.y; a2.z += q2.z; a2.w += q2.w;
        }
        const float r1 = 1.f / (float)(hi1 - lo1);
        const float r2 = 1.f / (float)(hi2 - lo2);
        float4 cls = xb[lane];           // row 0 (spans start >= 1)

        float4* __restrict__ fb = reinterpret_cast<float4*>(g_feat + (size_t)b*FF);
        fb[lane]            = make_float4(a1.x*r1, a1.y*r1, a1.z*r1, a1.w*r1);
        fb[(DD/4)   + lane] = make_float4(a2.x*r2, a2.y*r2, a2.z*r2, a2.w*r2);
        fb[2*(DD/4) + lane] = cls;
    }
}

// ---------------------------------------------------------------------------
// Kernel 2: fused 3-layer MLP + softmax. 128 CTAs x 512 threads, BT=8.
// Layer 1: manual 2-deep software pipeline (preload next k4 W1+feat regs
// while FMAing current) + single barrier per tile. Dynamic smem:
// fs [BT*FF] 73728 B + wbuf [2][KT*H1] 65536 B.
// ---------------------------------------------------------------------------
__global__ __launch_bounds__(NT) void mlp_kernel(
    const float* __restrict__ W1, const float* __restrict__ b1,
    const float* __restrict__ W2, const float* __restrict__ b2,
    const float* __restrict__ W3, const float* __restrict__ b3,
    float* __restrict__ out)
{
    extern __shared__ float fs[];          // [BT][FF]
    float* wbuf = fs + BT*FF;              // [2][KT*H1]
    __shared__ float h1s[BT][H1];
    __shared__ float h2s[BT][H2];

    const int b0  = blockIdx.x * BT;
    const int tid = threadIdx.x;

    // --- start W1 tile 0 prefetch immediately ---
    {
        #pragma unroll
        for (int i = 0; i < KT*H1/4/NT; ++i)   // 4 float4 per thread
            cp_async16(wbuf + (tid + i*NT)*4, W1 + (tid + i*NT)*4);
        cp_commit();
    }

    // --- load feat tile (coalesced float4 copy), overlaps with tile-0 fetch ---
    {
        const float4* __restrict__ src =
            reinterpret_cast<const float4*>(g_feat + (size_t)b0 * FF);
        float4* __restrict__ dst = reinterpret_cast<float4*>(fs);
        #pragma unroll
        for (int i = 0; i < BT*FF/4/NT; ++i)   // 9 per thread
            dst[tid + i*NT] = src[tid + i*NT];
    }

    // --- layer 1: [8,2304] @ [2304,256] ---
    {
        const int col = tid & (H1-1);
        const int g4  = (tid >> 8) * 4;

        float acc[4] = {0.f, 0.f, 0.f, 0.f};

        for (int t = 0; t < NTILE; ++t) {
            // tile t was committed in previous iteration (or prologue);
            // no other groups pending -> wait_group 0 waits exactly tile t.
            cp_wait<0>();
            __syncthreads();   // (a) tile t visible to all; (b) all warps done
                               // reading buf[(t-1)&1] == buf[(t+1)&1]

            if (t + 1 < NTILE) {     // issue tile t+1; overlaps compute below
                const float* src = W1 + (size_t)(t+1)*KT*H1;
                float* dst = wbuf + ((t+1)&1)*KT*H1;
                #pragma unroll
                for (int i = 0; i < KT*H1/4/NT; ++i)
                    cp_async16(dst + (tid + i*NT)*4, src + (tid + i*NT)*4);
                cp_commit();
            }

            const float* ws = wbuf + (t&1)*KT*H1;
            const float* fbase = fs + g4*FF + t*KT;

            // --- 2-deep software-pipelined k4 steps ---
            float  wA[4];
            float4 fA[4];
            #pragma unroll
            for (int q = 0; q < 4; ++q) wA[q] = ws[q*H1 + col];
            #pragma unroll
            for (int i = 0; i < 4; ++i)
                fA[i] = *reinterpret_cast<const float4*>(fbase + i*FF);

            #pragma unroll
            for (int kk = 0; kk < KT; kk += 4) {
                float  wB[4];
                float4 fB[4];
                if (kk + 4 < KT) {
                    #pragma unroll
                    for (int q = 0; q < 4; ++q)
                        wB[q] = ws[(kk+4+q)*H1 + col];
                    #pragma unroll
                    for (int i = 0; i < 4; ++i)
                        fB[i] = *reinterpret_cast<const float4*>(fbase + i*FF + kk + 4);
                }
                #pragma unroll
                for (int i = 0; i < 4; ++i) {
                    acc[i] = fmaf(fA[i].x, wA[0], acc[i]);
                    acc[i] = fmaf(fA[i].y, wA[1], acc[i]);
                    acc[i] = fmaf(fA[i].z, wA[2], acc[i]);
                    acc[i] = fmaf(fA[i].w, wA[3], acc[i]);
                }
                #pragma unroll
                for (int q = 0; q < 4; ++q) wA[q] = wB[q];
                #pragma unroll
                for (int i = 0; i < 4; ++i) fA[i] = fB[i];
            }
        }
        const float bb = b1[col];
        #pragma unroll
        for (int i = 0; i < 4; ++i)
            h1s[g4+i][col] = fmaxf(acc[i] + bb, 0.f);
    }
    __syncthreads();

    // --- layer 2: [8,256] @ [256,64]; one thread per (elem, col) ---
    {
        const int j = tid & (H2-1);
        const int i = tid >> 6;            // 0..7
        float a = 0.f;
        #pragma unroll 4
        for (int k = 0; k < H1; ++k)
            a = fmaf(h1s[i][k], W2[k*H2 + j], a);
        h2s[i][j] = fmaxf(a + b2[j], 0.f);
    }
    __syncthreads();

    // --- layer 3 + softmax: one thread per batch row ---
    if (tid < BT) {
        const int i = tid;
        float l0 = b3[0], l1 = b3[1], l2 = b3[2], l3 = b3[3];
        #pragma unroll 8
        for (int k = 0; k < H2; ++k) {
            const float h = h2s[i][k];
            l0 = fmaf(h, W3[k*NC+0], l0);
            l1 = fmaf(h, W3[k*NC+1], l1);
            l2 = fmaf(h, W3[k*NC+2], l2);
            l3 = fmaf(h, W3[k*NC+3], l3);
        }
        float m = fmaxf(fmaxf(l0,l1), fmaxf(l2,l3));
        float e0 = expf(l0 - m), e1x = expf(l1 - m),
              e2x = expf(l2 - m), e3 = expf(l3 - m);
        float inv = 1.f / (e0 + e1x + e2x + e3);
        float* o = out + (size_t)(b0 + i) * NC;
        o[0] = e0*inv; o[1] = e1x*inv; o[2] = e2x*inv; o[3] = e3*inv;
    }
}

// ---------------------------------------------------------------------------
extern "C" void kernel_launch(void* const* d_in, const int* in_sizes, int n_in,
                              void* d_out, int out_size)
{
    const float* x   = (const float*)d_in[0];
    const int*   e1  = (const int*)  d_in[1];
    const int*   e2  = (const int*)  d_in[2];
    const float* W1  = (const float*)d_in[3];
    const float* b1  = (const float*)d_in[4];
    const float* W2  = (const float*)d_in[5];
    const float* b2  = (const float*)d_in[6];
    const float* W3  = (const float*)d_in[7];
    const float* b3  = (const float*)d_in[8];
    float* out = (float*)d_out;

    static int smem_set = 0;
    const int smem_bytes = (BT*FF + 2*KT*H1) * (int)sizeof(float);  // 139264
    if (!smem_set) {
        cudaFuncSetAttribute(mlp_kernel,
            cudaFuncAttributeMaxDynamicSharedMemorySize, smem_bytes);
        smem_set = 1;
    }

    feat_kernel<<<BB, FNT>>>(x, e1, e2);
    mlp_kernel<<<BB/BT, NT, smem_bytes>>>(W1, b1, W2, b2, W3, b3, out);
}

// round 8
// speedup vs baseline: 3.3278x; 1.1265x over previous
#include <cuda_runtime.h>
#include <math.h>

// Problem constants (fixed-shape instance)
#define BB 1024
#define SS 512
#define DD 768
#define FF (3*DD)      // 2304
#define H1 256
#define H2 64
#define NC 4
#define BT 8           // batch rows per MLP CTA -> 128 CTAs
#define NT 512         // MLP threads per CTA
#define KT 32          // k-tile rows of W1 per cp.async stage
#define NTILE (FF/KT)  // 72
#define FG 4           // feat kernel row-groups
#define FNT (FG*192)   // 768 feat threads

// Scratch for feat = [e1 | e2 | cls], 1024 x 2304 fp32 (9.4 MB)
__device__ float g_feat[BB * FF];

// ---------------------------------------------------------------------------
// cp.async helpers (LDGSTS)
// ---------------------------------------------------------------------------
__device__ __forceinline__ void cp_async16(float* smem_dst, const float* gmem_src) {
    unsigned s = (unsigned)__cvta_generic_to_shared(smem_dst);
    asm volatile("cp.async.cg.shared.global [%0], [%1], 16;\n" :: "r"(s), "l"(gmem_src));
}
__device__ __forceinline__ void cp_commit() {
    asm volatile("cp.async.commit_group;\n" ::: "memory");
}
template<int N>
__device__ __forceinline__ void cp_wait() {
    asm volatile("cp.async.wait_group %0;\n" :: "n"(N) : "memory");
}

// ---------------------------------------------------------------------------
// Kernel 1: span means + cls. One CTA per batch element, 768 threads =
// 4 row-groups x 192 float4-lanes (at HBM roofline; unchanged from R6).
// ---------------------------------------------------------------------------
__global__ __launch_bounds__(FNT) void feat_kernel(
    const float* __restrict__ x,
    const int* __restrict__ e1,
    const int* __restrict__ e2)
{
    __shared__ float4 p1[FG][192];
    __shared__ float4 p2[FG][192];

    const int b    = blockIdx.x;
    const int tid  = threadIdx.x;
    const int g    = tid / 192;
    const int lane = tid % 192;

    int lo1 = e1[2*b]; int hi1 = max(e1[2*b+1], lo1 + 1);
    int lo2 = e2[2*b]; int hi2 = max(e2[2*b+1], lo2 + 1);

    const float4* __restrict__ xb =
        reinterpret_cast<const float4*>(x) + (size_t)b * (SS*(DD/4));

    float4 s1 = make_float4(0.f,0.f,0.f,0.f);
    float4 s2 = make_float4(0.f,0.f,0.f,0.f);

    auto rsum = [&](int a, int c, float4& acc) {
        #pragma unroll 4
        for (int s = a + g; s < c; s += FG) {
            float4 v = __ldcs(&xb[(size_t)s*(DD/4) + lane]);
            acc.x += v.x; acc.y += v.y; acc.z += v.z; acc.w += v.w;
        }
    };

    const int mlo = max(lo1, lo2);
    const int mhi = min(hi1, hi2);
    if (mlo < mhi) {          // overlapping spans: read overlap once
        float4 ov = make_float4(0.f,0.f,0.f,0.f);
        rsum(mlo, mhi, ov);
        rsum(lo1, mlo, s1); rsum(mhi, hi1, s1);
        rsum(lo2, mlo, s2); rsum(mhi, hi2, s2);
        s1.x += ov.x; s1.y += ov.y; s1.z += ov.z; s1.w += ov.w;
        s2.x += ov.x; s2.y += ov.y; s2.z += ov.z; s2.w += ov.w;
    } else {
        rsum(lo1, hi1, s1);
        rsum(lo2, hi2, s2);
    }

    p1[g][lane] = s1;
    p2[g][lane] = s2;
    __syncthreads();

    if (tid < 192) {
        float4 a1 = p1[0][lane], a2 = p2[0][lane];
        #pragma unroll
        for (int gg = 1; gg < FG; ++gg) {
            float4 q1 = p1[gg][lane], q2 = p2[gg][lane];
            a1.x += q1.x; a1.y += q1.y; a1.z += q1.z; a1.w += q1.w;
            a2.x += q2.x; a2.y += q2.y; a2.z += q2.z; a2.w += q2.w;
        }
        const float r1 = 1.f / (float)(hi1 - lo1);
        const float r2 = 1.f / (float)(hi2 - lo2);
        float4 cls = xb[lane];           // row 0 (spans start >= 1)

        float4* __restrict__ fb = reinterpret_cast<float4*>(g_feat + (size_t)b*FF);
        fb[lane]            = make_float4(a1.x*r1, a1.y*r1, a1.z*r1, a1.w*r1);
        fb[(DD/4)   + lane] = make_float4(a2.x*r2, a2.y*r2, a2.z*r2, a2.w*r2);
        fb[2*(DD/4) + lane] = cls;
    }
}

// ---------------------------------------------------------------------------
// Kernel 2: fused 3-layer MLP + softmax. 128 CTAs x 512 threads, BT=8.
// Layer 1 uses 4x4 register blocking with split-K over 4 thread groups:
//   tid -> kgrp (tid>>7, K-quarter of each tile), rowg ((tid>>6&1)*4),
//          c0 (((tid&63)*4) output cols).
// Per k4-step: 4 W1 LDS.128 + 4 feat LDS.128(broadcast) + 64 FFMA (8:1).
// Partials reduced across kgrps through smem.
// ---------------------------------------------------------------------------
__global__ __launch_bounds__(NT) void mlp_kernel(
    const float* __restrict__ W1, const float* __restrict__ b1,
    const float* __restrict__ W2, const float* __restrict__ b2,
    const float* __restrict__ W3, const float* __restrict__ b3,
    float* __restrict__ out)
{
    extern __shared__ float fs[];          // [BT][FF]        73728 B
    float* wbuf = fs + BT*FF;              // [2][KT*H1]      65536 B
    __shared__ float part[3][BT][H1];      // 24 KB (kgrp 1..3 partials)
    __shared__ float h1s[BT][H1];          // 8 KB
    __shared__ float h2s[BT][H2];          // 2 KB

    const int b0  = blockIdx.x * BT;
    const int tid = threadIdx.x;

    // --- start W1 tile 0 prefetch immediately ---
    {
        #pragma unroll
        for (int i = 0; i < KT*H1/4/NT; ++i)   // 4 float4 per thread
            cp_async16(wbuf + (tid + i*NT)*4, W1 + (tid + i*NT)*4);
        cp_commit();
    }

    // --- load feat tile (coalesced float4 copy), overlaps with tile-0 fetch ---
    {
        const float4* __restrict__ src =
            reinterpret_cast<const float4*>(g_feat + (size_t)b0 * FF);
        float4* __restrict__ dst = reinterpret_cast<float4*>(fs);
        #pragma unroll
        for (int i = 0; i < BT*FF/4/NT; ++i)   // 9 per thread
            dst[tid + i*NT] = src[tid + i*NT];
    }

    // --- layer 1: [8,2304] @ [2304,256], 4x4 register tiles, split-K x4 ---
    {
        const int kgrp = tid >> 7;             // 0..3: K-quarter of each tile
        const int r    = tid & 127;
        const int rowg = (r >> 6) * 4;         // 0 or 4
        const int c0   = (r & 63) * 4;         // 0,4,...,252 (warp-consecutive)

        float acc[4][4];
        #pragma unroll
        for (int i = 0; i < 4; ++i)
            #pragma unroll
            for (int j = 0; j < 4; ++j) acc[i][j] = 0.f;

        for (int t = 0; t < NTILE; ++t) {
            cp_wait<0>();
            __syncthreads();   // tile t visible; all warps done with buf[(t+1)&1]

            if (t + 1 < NTILE) {     // issue tile t+1; overlaps compute below
                const float* src = W1 + (size_t)(t+1)*KT*H1;
                float* dst = wbuf + ((t+1)&1)*KT*H1;
                #pragma unroll
                for (int i = 0; i < KT*H1/4/NT; ++i)
                    cp_async16(dst + (tid + i*NT)*4, src + (tid + i*NT)*4);
                cp_commit();
            }

            // this thread's K-quarter: 8 k-rows of the 32-row tile
            const float* ws = wbuf + (t&1)*KT*H1 + (kgrp*8)*H1;
            const float* fb = fs + rowg*FF + t*KT + kgrp*8;

            #pragma unroll
            for (int kq = 0; kq < 8; kq += 4) {
                float wv[4][4], fv[4][4];
                #pragma unroll
                for (int q = 0; q < 4; ++q) {
                    float4 w = *reinterpret_cast<const float4*>(ws + (kq+q)*H1 + c0);
                    wv[q][0]=w.x; wv[q][1]=w.y; wv[q][2]=w.z; wv[q][3]=w.w;
                }
                #pragma unroll
                for (int i = 0; i < 4; ++i) {
                    float4 f = *reinterpret_cast<const float4*>(fb + i*FF + kq);
                    fv[i][0]=f.x; fv[i][1]=f.y; fv[i][2]=f.z; fv[i][3]=f.w;
                }
                #pragma unroll
                for (int i = 0; i < 4; ++i)
                    #pragma unroll
                    for (int q = 0; q < 4; ++q)
                        #pragma unroll
                        for (int j = 0; j < 4; ++j)
                            acc[i][j] = fmaf(fv[i][q], wv[q][j], acc[i][j]);
            }
        }

        // --- cross-kgrp reduction ---
        if (kgrp > 0) {
            #pragma unroll
            for (int i = 0; i < 4; ++i)
                *reinterpret_cast<float4*>(&part[kgrp-1][rowg+i][c0]) =
                    make_float4(acc[i][0], acc[i][1], acc[i][2], acc[i][3]);
        }
        __syncthreads();
        if (kgrp == 0) {
            const float4 bb = *reinterpret_cast<const float4*>(b1 + c0);
            #pragma unroll
            for (int i = 0; i < 4; ++i) {
                float4 s = make_float4(acc[i][0], acc[i][1], acc[i][2], acc[i][3]);
                #pragma unroll
                for (int p = 0; p < 3; ++p) {
                    float4 q = *reinterpret_cast<const float4*>(&part[p][rowg+i][c0]);
                    s.x += q.x; s.y += q.y; s.z += q.z; s.w += q.w;
                }
                h1s[rowg+i][c0+0] = fmaxf(s.x + bb.x, 0.f);
                h1s[rowg+i][c0+1] = fmaxf(s.y + bb.y, 0.f);
                h1s[rowg+i][c0+2] = fmaxf(s.z + bb.z, 0.f);
                h1s[rowg+i][c0+3] = fmaxf(s.w + bb.w, 0.f);
            }
        }
    }
    __syncthreads();

    // --- layer 2: [8,256] @ [256,64]; one thread per (elem, col) ---
    {
        const int j = tid & (H2-1);
        const int i = tid >> 6;            // 0..7
        float a = 0.f;
        #pragma unroll 4
        for (int k = 0; k < H1; ++k)
            a = fmaf(h1s[i][k], W2[k*H2 + j], a);
        h2s[i][j] = fmaxf(a + b2[j], 0.f);
    }
    __syncthreads();

    // --- layer 3 + softmax: one thread per batch row ---
    if (tid < BT) {
        const int i = tid;
        float l0 = b3[0], l1 = b3[1], l2 = b3[2], l3 = b3[3];
        #pragma unroll 8
        for (int k = 0; k < H2; ++k) {
            const float h = h2s[i][k];
            l0 = fmaf(h, W3[k*NC+0], l0);
            l1 = fmaf(h, W3[k*NC+1], l1);
            l2 = fmaf(h, W3[k*NC+2], l2);
            l3 = fmaf(h, W3[k*NC+3], l3);
        }
        float m = fmaxf(fmaxf(l0,l1), fmaxf(l2,l3));
        float e0 = expf(l0 - m), e1x = expf(l1 - m),
              e2x = expf(l2 - m), e3 = expf(l3 - m);
        float inv = 1.f / (e0 + e1x + e2x + e3);
        float* o = out + (size_t)(b0 + i) * NC;
        o[0] = e0*inv; o[1] = e1x*inv; o[2] = e2x*inv; o[3] = e3*inv;
    }
}

// ---------------------------------------------------------------------------
extern "C" void kernel_launch(void* const* d_in, const int* in_sizes, int n_in,
                              void* d_out, int out_size)
{
    const float* x   = (const float*)d_in[0];
    const int*   e1  = (const int*)  d_in[1];
    const int*   e2  = (const int*)  d_in[2];
    const float* W1  = (const float*)d_in[3];
    const float* b1  = (const float*)d_in[4];
    const float* W2  = (const float*)d_in[5];
    const float* b2  = (const float*)d_in[6];
    const float* W3  = (const float*)d_in[7];
    const float* b3  = (const float*)d_in[8];
    float* out = (float*)d_out;

    static int smem_set = 0;
    const int smem_bytes = (BT*FF + 2*KT*H1) * (int)sizeof(float);  // 139264
    if (!smem_set) {
        cudaFuncSetAttribute(mlp_kernel,
            cudaFuncAttributeMaxDynamicSharedMemorySize, smem_bytes);
        smem_set = 1;
    }

    feat_kernel<<<BB, FNT>>>(x, e1, e2);
    mlp_kernel<<<BB/BT, NT, smem_bytes>>>(W1, b1, W2, b2, W3, b3, out);
}